// round 3
// baseline (speedup 1.0000x reference)
#include <cuda_runtime.h>
#include <cuda_fp16.h>
#include <cstdint>
#include <cstddef>

// ---------------------------------------------------------------------------
// FeedForwardQuantum on base sm_100 (no tcgen05 on this build target!):
//   out[32768,1024] = relu(cos(x[:, :10]) @ W1^T + b1) @ W2^T + b2
// Path: mma.sync.m16n8k16 fp16 tensor cores, 2-product split:
//   h = h_hi + h_lo (fp16 each, 22-bit effective), W2 single fp16.
//   out = h_hi@W2f + h_lo@W2f  (fp32 accum)  -> rel err ~ 2.8e-4 (W2 rounding)
// ---------------------------------------------------------------------------

#define NTOK 32768
#define EDIM 1024
#define FDIM 1024
#define NQD  10

// scratch
static __device__ __align__(1024) __half g_h_hi[(size_t)NTOK * FDIM]; // 64 MB
static __device__ __align__(1024) __half g_h_lo[(size_t)NTOK * FDIM]; // 64 MB
static __device__ __align__(1024) __half g_w[(size_t)EDIM * FDIM];    //  2 MB

// ------------------------------- helpers -----------------------------------
__device__ __forceinline__ uint32_t smem_u32(const void* p) {
    return (uint32_t)__cvta_generic_to_shared(p);
}
__device__ __forceinline__ void cp_async16(uint32_t dst, const void* src) {
    asm volatile("cp.async.cg.shared.global [%0], [%1], 16;\n" :: "r"(dst), "l"(src));
}
__device__ __forceinline__ void cp_commit() {
    asm volatile("cp.async.commit_group;\n");
}
template <int N>
__device__ __forceinline__ void cp_wait() {
    asm volatile("cp.async.wait_group %0;\n" :: "n"(N));
}
__device__ __forceinline__ void ldsm_x4(uint32_t& r0, uint32_t& r1, uint32_t& r2,
                                        uint32_t& r3, uint32_t addr) {
    asm volatile("ldmatrix.sync.aligned.m8n8.x4.shared.b16 {%0,%1,%2,%3}, [%4];"
                 : "=r"(r0), "=r"(r1), "=r"(r2), "=r"(r3) : "r"(addr));
}
__device__ __forceinline__ void mma16816(float* c, const uint32_t* a, const uint32_t* b) {
    asm volatile(
        "mma.sync.aligned.m16n8k16.row.col.f32.f16.f16.f32 "
        "{%0,%1,%2,%3}, {%4,%5,%6,%7}, {%8,%9}, {%0,%1,%2,%3};"
        : "+f"(c[0]), "+f"(c[1]), "+f"(c[2]), "+f"(c[3])
        : "r"(a[0]), "r"(a[1]), "r"(a[2]), "r"(a[3]), "r"(b[0]), "r"(b[1]));
}
__device__ __forceinline__ uint32_t pack_h2(__half a, __half b) {
    __half2 t = __halves2half2(a, b);
    return *reinterpret_cast<uint32_t*>(&t);
}

// ---------------------------------------------------------------------------
// K0: W2 [1024,1024] fp32 -> fp16
// ---------------------------------------------------------------------------
__global__ __launch_bounds__(256) void prep_w2_kernel(const float* __restrict__ W2) {
    size_t i = ((size_t)blockIdx.x * 256 + threadIdx.x) * 4;
    float4 v = *reinterpret_cast<const float4*>(W2 + i);
    uint2 hv;
    hv.x = pack_h2(__float2half(v.x), __float2half(v.y));
    hv.y = pack_h2(__float2half(v.z), __float2half(v.w));
    *reinterpret_cast<uint2*>(&g_w[i]) = hv;
}

// ---------------------------------------------------------------------------
// K1: h = relu(cos(x[:, :10]) @ W1^T + b1) -> fp16 hi + fp16 lo
// block: 128 tokens x full F=1024; thread owns 4 features.
// ---------------------------------------------------------------------------
__global__ __launch_bounds__(256) void prep_h_kernel(const float* __restrict__ x,
                                                     const float* __restrict__ W1,
                                                     const float* __restrict__ b1) {
    __shared__ float cz[128 * NQD];
    const int tid = threadIdx.x;
    const int m0 = blockIdx.x * 128;

    for (int idx = tid; idx < 128 * NQD; idx += 256) {
        int t = idx / NQD, q = idx % NQD;
        cz[idx] = cosf(x[(size_t)(m0 + t) * EDIM + q]);
    }

    const int f0 = tid * 4;
    float w[4][NQD], bb[4];
#pragma unroll
    for (int i = 0; i < 4; i++) {
        bb[i] = b1[f0 + i];
#pragma unroll
        for (int q = 0; q < NQD; q++) w[i][q] = W1[(f0 + i) * NQD + q];
    }
    __syncthreads();

    for (int t = 0; t < 128; t++) {
        float z[NQD];
#pragma unroll
        for (int q = 0; q < NQD; q++) z[q] = cz[t * NQD + q];
        __half hh[4], hl[4];
#pragma unroll
        for (int i = 0; i < 4; i++) {
            float acc = bb[i];
#pragma unroll
            for (int q = 0; q < NQD; q++) acc = fmaf(z[q], w[i][q], acc);
            acc = fmaxf(acc, 0.0f);
            __half h = __float2half(acc);
            hh[i] = h;
            hl[i] = __float2half(acc - __half2float(h));
        }
        size_t base = (size_t)(m0 + t) * FDIM + f0;
        uint2 hv; hv.x = pack_h2(hh[0], hh[1]); hv.y = pack_h2(hh[2], hh[3]);
        uint2 lv; lv.x = pack_h2(hl[0], hl[1]); lv.y = pack_h2(hl[2], hl[3]);
        *reinterpret_cast<uint2*>(&g_h_hi[base]) = hv;
        *reinterpret_cast<uint2*>(&g_h_lo[base]) = lv;
    }
}

// ---------------------------------------------------------------------------
// K2: GEMM  out[m,e] = sum_f h[m,f]*W2[e,f] + b2[e]
//   CTA tile 128(M) x 256(N), K-chunk 64, 3-stage cp.async pipeline.
//   8 warps in 2(M) x 4(N) grid -> warp tile 64x64.
//   SW128 swizzle (off ^= ((off>>3)&0x70), rows are 128B = 64 fp16).
// ---------------------------------------------------------------------------
#define MT 128
#define NT 256
#define KC 64
#define NCHUNK (FDIM / KC) // 16
#define STAGES 3
#define OFF_ALOs 16384
#define OFF_Bs   32768
#define STAGE_BYTES 65536
#define GEMM_SMEM (STAGES * STAGE_BYTES) // 196,608 B

__global__ __launch_bounds__(256, 1) void gemm2_kernel(float* __restrict__ out,
                                                       const float* __restrict__ b2) {
    extern __shared__ __align__(1024) char smem[];
    const uint32_t sb = smem_u32(smem);
    const int tid = threadIdx.x;
    const int wid = tid >> 5;
    const int lane = tid & 31;
    const int m0 = blockIdx.y * MT;
    const int n0t = blockIdx.x * NT;

    const int warpM = (wid & 1) * 64;
    const int warpN = (wid >> 1) * 64;

    // ---- cp.async geometry: thread -> (row r+32i, 16B-chunk c16) ----
    const int r = tid >> 3;   // 0..31
    const int c16 = tid & 7;  // 0..7
    const uint32_t dswz = (uint32_t)(r * 128) + (((uint32_t)(c16 * 16)) ^ ((uint32_t)(r & 7) << 4));
    const size_t gA = (size_t)(m0 + r) * FDIM + (size_t)(c16 * 8);
    const size_t gB = (size_t)(n0t + r) * FDIM + (size_t)(c16 * 8);

    auto load_chunk = [&](int stage, int c) {
        const uint32_t st = sb + stage * STAGE_BYTES;
        const size_t ko = (size_t)c * KC;
#pragma unroll
        for (int i = 0; i < 4; i++) { // A: 128 rows (hi & lo)
            cp_async16(st + dswz + i * 4096, g_h_hi + gA + ko + (size_t)i * 32 * FDIM);
            cp_async16(st + OFF_ALOs + dswz + i * 4096, g_h_lo + gA + ko + (size_t)i * 32 * FDIM);
        }
#pragma unroll
        for (int i = 0; i < 8; i++) { // B: 256 rows
            cp_async16(st + OFF_Bs + dswz + i * 4096, g_w + gB + ko + (size_t)i * 32 * FDIM);
        }
        cp_commit();
    };

    // ---- ldmatrix geometry ----
    const int r_lane = lane & 7;
    const int grp = lane >> 3;
    const uint32_t xr = (uint32_t)(r_lane << 4);
    // A mats: grp0:(m-lo,k-lo) grp1:(m-hi,k-lo) grp2:(m-lo,k-hi) grp3:(m-hi,k-hi)
    const int aRow = warpM + (grp & 1) * 8 + r_lane;
    const uint32_t aColSel = (uint32_t)((grp >> 1) * 16);
    // B mats: grp0:(n-sub0,k-lo) grp1:(n-sub0,k-hi) grp2:(n-sub1,k-lo) grp3:(n-sub1,k-hi)
    const int bRow = warpN + (grp >> 1) * 8 + r_lane;
    const uint32_t bColSel = (uint32_t)((grp & 1) * 16);

    float acc[4][8][4];
#pragma unroll
    for (int i = 0; i < 4; i++)
#pragma unroll
        for (int j = 0; j < 8; j++)
#pragma unroll
            for (int k = 0; k < 4; k++) acc[i][j][k] = 0.0f;

    // ---- prologue ----
    load_chunk(0, 0);
    load_chunk(1, 1);

    // ---- main loop ----
    for (int c = 0; c < NCHUNK; ++c) {
        if (c + 2 < NCHUNK) {
            load_chunk((c + 2) % STAGES, c + 2);
            cp_wait<2>();
        } else if (c + 1 < NCHUNK) {
            cp_wait<1>();
        } else {
            cp_wait<0>();
        }
        __syncthreads();

        const uint32_t st = sb + (c % STAGES) * STAGE_BYTES;
#pragma unroll
        for (int ks = 0; ks < 4; ks++) {
            const uint32_t colA = ((uint32_t)(ks * 32) + aColSel) ^ xr;
            const uint32_t colB = ((uint32_t)(ks * 32) + bColSel) ^ xr;
            uint32_t ah[4][4], al[4][4], bf[8][2];
#pragma unroll
            for (int mt = 0; mt < 4; mt++) {
                const uint32_t ra = st + (uint32_t)((aRow + mt * 16) * 128) + colA;
                ldsm_x4(ah[mt][0], ah[mt][1], ah[mt][2], ah[mt][3], ra);
                ldsm_x4(al[mt][0], al[mt][1], al[mt][2], al[mt][3], ra + OFF_ALOs);
            }
#pragma unroll
            for (int np = 0; np < 4; np++) {
                const uint32_t rb = st + OFF_Bs + (uint32_t)((bRow + np * 16) * 128) + colB;
                uint32_t q0, q1, q2, q3;
                ldsm_x4(q0, q1, q2, q3, rb);
                bf[np * 2][0] = q0; bf[np * 2][1] = q1;
                bf[np * 2 + 1][0] = q2; bf[np * 2 + 1][1] = q3;
            }
#pragma unroll
            for (int mt = 0; mt < 4; mt++)
#pragma unroll
                for (int nt = 0; nt < 8; nt++) {
                    mma16816(acc[mt][nt], ah[mt], bf[nt]);
                    mma16816(acc[mt][nt], al[mt], bf[nt]);
                }
        }
        __syncthreads(); // all warps done with stage c%3 before it is refilled
    }

    // ---- epilogue: direct stores with bias ----
    const int cr = lane >> 2;          // 0..7
    const int cc = (lane & 3) * 2;     // 0,2,4,6
#pragma unroll
    for (int nt = 0; nt < 8; nt++) {
        const int col = n0t + warpN + nt * 8 + cc;
        const float bx = b2[col], by = b2[col + 1];
#pragma unroll
        for (int mt = 0; mt < 4; mt++) {
            const int row0 = m0 + warpM + mt * 16 + cr;
            float2 v0 = make_float2(acc[mt][nt][0] + bx, acc[mt][nt][1] + by);
            float2 v1 = make_float2(acc[mt][nt][2] + bx, acc[mt][nt][3] + by);
            *reinterpret_cast<float2*>(out + (size_t)row0 * EDIM + col) = v0;
            *reinterpret_cast<float2*>(out + (size_t)(row0 + 8) * EDIM + col) = v1;
        }
    }
}

// ---------------------------------------------------------------------------
// kernel_launch
// inputs: x[33554432], rz_theta[10](unused), W1[10240], b1[1024],
//         W2[1048576], b2[1024]; out fp32 [33554432]
// ---------------------------------------------------------------------------
extern "C" void kernel_launch(void* const* d_in, const int* in_sizes, int n_in,
                              void* d_out, int out_size) {
    (void)in_sizes; (void)n_in; (void)out_size;
    const float* x  = (const float*)d_in[0];
    const float* W1 = (const float*)d_in[2];
    const float* b1 = (const float*)d_in[3];
    const float* W2 = (const float*)d_in[4];
    const float* b2 = (const float*)d_in[5];
    float* out = (float*)d_out;

    cudaFuncSetAttribute(gemm2_kernel, cudaFuncAttributeMaxDynamicSharedMemorySize, GEMM_SMEM);

    prep_w2_kernel<<<1024, 256>>>(W2);
    prep_h_kernel<<<NTOK / 128, 256>>>(x, W1, b1);
    gemm2_kernel<<<dim3(EDIM / NT, NTOK / MT), 256, GEMM_SMEM>>>(out, b2);
}

// round 4
// speedup vs baseline: 1.6387x; 1.6387x over previous
#include <cuda_runtime.h>
#include <cuda_fp16.h>
#include <cstdint>
#include <cstddef>

// ---------------------------------------------------------------------------
// FeedForwardQuantum on base sm_100 target (no tcgen05 on this build):
//   out[32768,1024] = relu(cos(x[:, :10]) @ W1^T + b1) @ W2^T + b2
// mma.sync.m16n8k16 fp16 tensor cores, single product:
//   h -> fp16, W2 -> fp16, fp32 accum.
//   Measured: W2-fp16 alone gives rel_err 2.0e-4; h-fp16 adds an independent
//   equal term -> predicted ~2.8e-4, threshold 1e-3.
// ---------------------------------------------------------------------------

#define NTOK 32768
#define EDIM 1024
#define FDIM 1024
#define NQD  10

// scratch
static __device__ __align__(1024) __half g_h[(size_t)NTOK * FDIM]; // 64 MB
static __device__ __align__(1024) __half g_w[(size_t)EDIM * FDIM]; //  2 MB

// ------------------------------- helpers -----------------------------------
__device__ __forceinline__ uint32_t smem_u32(const void* p) {
    return (uint32_t)__cvta_generic_to_shared(p);
}
__device__ __forceinline__ void cp_async16(uint32_t dst, const void* src) {
    asm volatile("cp.async.cg.shared.global [%0], [%1], 16;\n" :: "r"(dst), "l"(src));
}
__device__ __forceinline__ void cp_commit() {
    asm volatile("cp.async.commit_group;\n");
}
template <int N>
__device__ __forceinline__ void cp_wait() {
    asm volatile("cp.async.wait_group %0;\n" :: "n"(N));
}
__device__ __forceinline__ void ldsm_x4(uint32_t& r0, uint32_t& r1, uint32_t& r2,
                                        uint32_t& r3, uint32_t addr) {
    asm volatile("ldmatrix.sync.aligned.m8n8.x4.shared.b16 {%0,%1,%2,%3}, [%4];"
                 : "=r"(r0), "=r"(r1), "=r"(r2), "=r"(r3) : "r"(addr));
}
__device__ __forceinline__ void mma16816(float* c, const uint32_t* a, const uint32_t* b) {
    asm volatile(
        "mma.sync.aligned.m16n8k16.row.col.f32.f16.f16.f32 "
        "{%0,%1,%2,%3}, {%4,%5,%6,%7}, {%8,%9}, {%0,%1,%2,%3};"
        : "+f"(c[0]), "+f"(c[1]), "+f"(c[2]), "+f"(c[3])
        : "r"(a[0]), "r"(a[1]), "r"(a[2]), "r"(a[3]), "r"(b[0]), "r"(b[1]));
}
__device__ __forceinline__ uint32_t pack_h2(__half a, __half b) {
    __half2 t = __halves2half2(a, b);
    return *reinterpret_cast<uint32_t*>(&t);
}

// ---------------------------------------------------------------------------
// K0: W2 [1024,1024] fp32 -> fp16
// ---------------------------------------------------------------------------
__global__ __launch_bounds__(256) void prep_w2_kernel(const float* __restrict__ W2) {
    size_t i = ((size_t)blockIdx.x * 256 + threadIdx.x) * 4;
    float4 v = *reinterpret_cast<const float4*>(W2 + i);
    uint2 hv;
    hv.x = pack_h2(__float2half(v.x), __float2half(v.y));
    hv.y = pack_h2(__float2half(v.z), __float2half(v.w));
    *reinterpret_cast<uint2*>(&g_w[i]) = hv;
}

// ---------------------------------------------------------------------------
// K1: h = relu(cos(x[:, :10]) @ W1^T + b1) -> fp16
// block: 128 tokens x full F=1024; thread owns 4 features.
// ---------------------------------------------------------------------------
__global__ __launch_bounds__(256) void prep_h_kernel(const float* __restrict__ x,
                                                     const float* __restrict__ W1,
                                                     const float* __restrict__ b1) {
    __shared__ float cz[128 * NQD];
    const int tid = threadIdx.x;
    const int m0 = blockIdx.x * 128;

    for (int idx = tid; idx < 128 * NQD; idx += 256) {
        int t = idx / NQD, q = idx % NQD;
        cz[idx] = cosf(x[(size_t)(m0 + t) * EDIM + q]);
    }

    const int f0 = tid * 4;
    float w[4][NQD], bb[4];
#pragma unroll
    for (int i = 0; i < 4; i++) {
        bb[i] = b1[f0 + i];
#pragma unroll
        for (int q = 0; q < NQD; q++) w[i][q] = W1[(f0 + i) * NQD + q];
    }
    __syncthreads();

    for (int t = 0; t < 128; t++) {
        float z[NQD];
#pragma unroll
        for (int q = 0; q < NQD; q++) z[q] = cz[t * NQD + q];
        __half hh[4];
#pragma unroll
        for (int i = 0; i < 4; i++) {
            float acc = bb[i];
#pragma unroll
            for (int q = 0; q < NQD; q++) acc = fmaf(z[q], w[i][q], acc);
            hh[i] = __float2half(fmaxf(acc, 0.0f));
        }
        size_t base = (size_t)(m0 + t) * FDIM + f0;
        uint2 hv; hv.x = pack_h2(hh[0], hh[1]); hv.y = pack_h2(hh[2], hh[3]);
        *reinterpret_cast<uint2*>(&g_h[base]) = hv;
    }
}

// ---------------------------------------------------------------------------
// K2: GEMM  out[m,e] = sum_f h[m,f]*W2[e,f] + b2[e]
//   CTA tile 128(M) x 256(N), K-chunk 64, 4-stage cp.async pipeline.
//   8 warps in 2(M) x 4(N) grid -> warp tile 64x64.
//   SW128 swizzle (off ^= ((off>>3)&0x70)); rows are 128B = 64 fp16.
// ---------------------------------------------------------------------------
#define MT 128
#define NT 256
#define KC 64
#define NCHUNK (FDIM / KC) // 16
#define STAGES 4
#define OFF_Bs   16384
#define STAGE_BYTES 49152
#define GEMM_SMEM (STAGES * STAGE_BYTES) // 196,608 B

__global__ __launch_bounds__(256, 1) void gemm2_kernel(float* __restrict__ out,
                                                       const float* __restrict__ b2) {
    extern __shared__ __align__(1024) char smem[];
    const uint32_t sb = smem_u32(smem);
    const int tid = threadIdx.x;
    const int wid = tid >> 5;
    const int lane = tid & 31;
    const int m0 = blockIdx.y * MT;
    const int n0t = blockIdx.x * NT;

    const int warpM = (wid & 1) * 64;
    const int warpN = (wid >> 1) * 64;

    // ---- cp.async geometry: thread -> (row r+32i, 16B-chunk c16) ----
    const int r = tid >> 3;   // 0..31
    const int c16 = tid & 7;  // 0..7
    const uint32_t dswz = (uint32_t)(r * 128) + (((uint32_t)(c16 * 16)) ^ ((uint32_t)(r & 7) << 4));
    const size_t gA = (size_t)(m0 + r) * FDIM + (size_t)(c16 * 8);
    const size_t gB = (size_t)(n0t + r) * FDIM + (size_t)(c16 * 8);

    auto load_chunk = [&](int stage, int c) {
        const uint32_t st = sb + stage * STAGE_BYTES;
        const size_t ko = (size_t)c * KC;
#pragma unroll
        for (int i = 0; i < 4; i++) { // A: 128 rows
            cp_async16(st + dswz + i * 4096, g_h + gA + ko + (size_t)i * 32 * FDIM);
        }
#pragma unroll
        for (int i = 0; i < 8; i++) { // B: 256 rows
            cp_async16(st + OFF_Bs + dswz + i * 4096, g_w + gB + ko + (size_t)i * 32 * FDIM);
        }
        cp_commit();
    };

    // ---- ldmatrix geometry ----
    const int r_lane = lane & 7;
    const int grp = lane >> 3;
    const uint32_t xr = (uint32_t)(r_lane << 4);
    // A mats: grp0:(m-lo,k-lo) grp1:(m-hi,k-lo) grp2:(m-lo,k-hi) grp3:(m-hi,k-hi)
    const int aRow = warpM + (grp & 1) * 8 + r_lane;
    const uint32_t aColSel = (uint32_t)((grp >> 1) * 16);
    // B mats: grp0:(n-sub0,k-lo) grp1:(n-sub0,k-hi) grp2:(n-sub1,k-lo) grp3:(n-sub1,k-hi)
    const int bRow = warpN + (grp >> 1) * 8 + r_lane;
    const uint32_t bColSel = (uint32_t)((grp & 1) * 16);

    float acc[4][8][4];
#pragma unroll
    for (int i = 0; i < 4; i++)
#pragma unroll
        for (int j = 0; j < 8; j++)
#pragma unroll
            for (int k = 0; k < 4; k++) acc[i][j][k] = 0.0f;

    // ---- prologue: prefetch 3 chunks ----
    load_chunk(0, 0);
    load_chunk(1, 1);
    load_chunk(2, 2);

    // ---- main loop ----
    for (int c = 0; c < NCHUNK; ++c) {
        if (c + 3 < NCHUNK) {
            load_chunk((c + 3) % STAGES, c + 3);
            cp_wait<3>();
        } else if (c + 2 < NCHUNK) {
            cp_wait<2>();
        } else if (c + 1 < NCHUNK) {
            cp_wait<1>();
        } else {
            cp_wait<0>();
        }
        __syncthreads();

        const uint32_t st = sb + (c % STAGES) * STAGE_BYTES;
#pragma unroll
        for (int ks = 0; ks < 4; ks++) {
            const uint32_t colA = ((uint32_t)(ks * 32) + aColSel) ^ xr;
            const uint32_t colB = ((uint32_t)(ks * 32) + bColSel) ^ xr;
            uint32_t ah[4][4], bf[8][2];
#pragma unroll
            for (int mt = 0; mt < 4; mt++) {
                const uint32_t ra = st + (uint32_t)((aRow + mt * 16) * 128) + colA;
                ldsm_x4(ah[mt][0], ah[mt][1], ah[mt][2], ah[mt][3], ra);
            }
#pragma unroll
            for (int np = 0; np < 4; np++) {
                const uint32_t rb = st + OFF_Bs + (uint32_t)((bRow + np * 16) * 128) + colB;
                uint32_t q0, q1, q2, q3;
                ldsm_x4(q0, q1, q2, q3, rb);
                bf[np * 2][0] = q0; bf[np * 2][1] = q1;
                bf[np * 2 + 1][0] = q2; bf[np * 2 + 1][1] = q3;
            }
#pragma unroll
            for (int mt = 0; mt < 4; mt++)
#pragma unroll
                for (int nt = 0; nt < 8; nt++) {
                    mma16816(acc[mt][nt], ah[mt], bf[nt]);
                }
        }
        __syncthreads(); // all warps done with stage c%STAGES before refill
    }

    // ---- epilogue: direct stores with bias ----
    const int cr = lane >> 2;          // 0..7
    const int cc = (lane & 3) * 2;     // 0,2,4,6
#pragma unroll
    for (int nt = 0; nt < 8; nt++) {
        const int col = n0t + warpN + nt * 8 + cc;
        const float bx = b2[col], by = b2[col + 1];
#pragma unroll
        for (int mt = 0; mt < 4; mt++) {
            const int row0 = m0 + warpM + mt * 16 + cr;
            float2 v0 = make_float2(acc[mt][nt][0] + bx, acc[mt][nt][1] + by);
            float2 v1 = make_float2(acc[mt][nt][2] + bx, acc[mt][nt][3] + by);
            *reinterpret_cast<float2*>(out + (size_t)row0 * EDIM + col) = v0;
            *reinterpret_cast<float2*>(out + (size_t)(row0 + 8) * EDIM + col) = v1;
        }
    }
}

// ---------------------------------------------------------------------------
// kernel_launch
// inputs: x[33554432], rz_theta[10](unused), W1[10240], b1[1024],
//         W2[1048576], b2[1024]; out fp32 [33554432]
// ---------------------------------------------------------------------------
extern "C" void kernel_launch(void* const* d_in, const int* in_sizes, int n_in,
                              void* d_out, int out_size) {
    (void)in_sizes; (void)n_in; (void)out_size;
    const float* x  = (const float*)d_in[0];
    const float* W1 = (const float*)d_in[2];
    const float* b1 = (const float*)d_in[3];
    const float* W2 = (const float*)d_in[4];
    const float* b2 = (const float*)d_in[5];
    float* out = (float*)d_out;

    cudaFuncSetAttribute(gemm2_kernel, cudaFuncAttributeMaxDynamicSharedMemorySize, GEMM_SMEM);

    prep_w2_kernel<<<1024, 256>>>(W2);
    prep_h_kernel<<<NTOK / 128, 256>>>(x, W1, b1);
    gemm2_kernel<<<dim3(EDIM / NT, NTOK / MT), 256, GEMM_SMEM>>>(out, b2);
}